// round 5
// baseline (speedup 1.0000x reference)
#include <cuda_runtime.h>
#include <cstdint>

#define TOK 16384
#define DID 1024
#define HID 4096
#define NE  8

// k-interleave within each 32-chunk: slot = (k%4)*8 + k/4
#define SIGMA(t) ((((t) & 3) << 3) | ((t) >> 2))

// ---------------- scratch ---------------------------------------------------
__device__ int   g_count[NE];
__device__ int   g_off[NE];                       // 128-aligned cumulative
__device__ __align__(16) int   g_list[NE][TOK];
__device__ __align__(16) float g_wlist[NE][TOK];
__device__ __align__(256) float g_xr[(size_t)TOK * DID];         // rounded+interleaved x
__device__ __align__(256) float g_wt1[(size_t)NE * HID * DID];   // W1^T [e][n][k]
__device__ __align__(256) float g_wt2[(size_t)NE * DID * HID];   // W2^T [e][n][k]
__device__ __align__(256) float g_hidden[(size_t)(2 * TOK + NE * 128) * HID];

// ---------------- helpers ---------------------------------------------------
__device__ __forceinline__ float f2tf_f(float f) {
    uint32_t r;
    asm("cvt.rna.tf32.f32 %0, %1;" : "=r"(r) : "f"(f));
    return __uint_as_float(r);
}
__device__ __forceinline__ uint32_t smem_u32(const void* p) {
    uint32_t a;
    asm("{ .reg .u64 t; cvta.to.shared.u64 t, %1; cvt.u32.u64 %0, t; }" : "=r"(a) : "l"(p));
    return a;
}
__device__ __forceinline__ void cpa16(uint32_t s, const void* g) {
    asm volatile("cp.async.cg.shared.global [%0], [%1], 16;\n" ::"r"(s), "l"(g));
}
__device__ __forceinline__ void mma_tf32x(float* c, float a0, float a1, float a2,
                                          float a3, float b0, float b1) {
    asm volatile(
        "mma.sync.aligned.m16n8k8.row.col.f32.tf32.tf32.f32 "
        "{%0,%1,%2,%3},{%4,%5,%6,%7},{%8,%9},{%0,%1,%2,%3};"
        : "+f"(c[0]), "+f"(c[1]), "+f"(c[2]), "+f"(c[3])
        : "r"(__float_as_uint(a0)), "r"(__float_as_uint(a1)),
          "r"(__float_as_uint(a2)), "r"(__float_as_uint(a3)),
          "r"(__float_as_uint(b0)), "r"(__float_as_uint(b1)));
}

// ---------------- gate ------------------------------------------------------
__global__ void gate_kernel(const float* __restrict__ x,
                            const float* __restrict__ gw,
                            const float* __restrict__ gb) {
    int warp = (blockIdx.x * blockDim.x + threadIdx.x) >> 5;
    int lane = threadIdx.x & 31;
    if (warp >= TOK) return;
    const float* xr = x + (size_t)warp * DID;
    float p[NE];
#pragma unroll
    for (int e = 0; e < NE; e++) p[e] = 0.f;
#pragma unroll 4
    for (int i = 0; i < DID / 32; i++) {
        int d = i * 32 + lane;
        float xv = xr[d];
        const float4* g4 = reinterpret_cast<const float4*>(gw + (size_t)d * NE);
        float4 g0 = g4[0], g1 = g4[1];
        p[0] += xv * g0.x; p[1] += xv * g0.y; p[2] += xv * g0.z; p[3] += xv * g0.w;
        p[4] += xv * g1.x; p[5] += xv * g1.y; p[6] += xv * g1.z; p[7] += xv * g1.w;
    }
#pragma unroll
    for (int e = 0; e < NE; e++)
#pragma unroll
        for (int o = 16; o > 0; o >>= 1) p[e] += __shfl_xor_sync(0xffffffffu, p[e], o);
    if (lane == 0) {
        float l[NE];
#pragma unroll
        for (int e = 0; e < NE; e++) l[e] = p[e] + gb[e];
        int e0 = 0, e1 = -1;
        float b0 = l[0], b1 = -3.0e38f;
#pragma unroll
        for (int e = 1; e < NE; e++) {
            float v = l[e];
            if (v > b0)      { b1 = b0; e1 = e0; b0 = v; e0 = e; }
            else if (v > b1) { b1 = v;  e1 = e; }
        }
        float ex = expf(b1 - b0);
        float inv = 1.f / (1.f + ex);
        int p0 = atomicAdd(&g_count[e0], 1);
        g_list[e0][p0] = warp; g_wlist[e0][p0] = inv;
        int p1 = atomicAdd(&g_count[e1], 1);
        g_list[e1][p1] = warp; g_wlist[e1][p1] = ex * inv;
    }
}

__global__ void offs_kernel() {
    int s = 0;
#pragma unroll
    for (int e = 0; e < NE; e++) { g_off[e] = s; s += (g_count[e] + 127) & ~127; }
}

// ---------------- pre-passes ------------------------------------------------
// x -> tf32-rounded, k-interleaved per 32-chunk
__global__ void round_x_kernel(const float4* __restrict__ in) {
    int n4 = TOK * DID / 4;
    for (int i = blockIdx.x * blockDim.x + threadIdx.x; i < n4;
         i += gridDim.x * blockDim.x) {
        float4 v = in[i];
        int base = (i << 2) & ~31;
        int t = i & 7;                       // SIGMA(4t+j) = j*8+t
        g_xr[base + t]      = f2tf_f(v.x);
        g_xr[base + 8 + t]  = f2tf_f(v.y);
        g_xr[base + 16 + t] = f2tf_f(v.z);
        g_xr[base + 24 + t] = f2tf_f(v.w);
    }
}

// W [e][Kd][Nd] -> Wt [e][Nd][Kd], rounded + k-interleaved
__global__ void transpose_w(const float* __restrict__ W, float* __restrict__ Wt,
                            int Kd, int Nd) {
    __shared__ float t[32][33];
    int e = blockIdx.z;
    int n0 = blockIdx.x * 32, k0 = blockIdx.y * 32;
    const float* Wb = W + (size_t)e * Kd * Nd;
    float* Wtb = Wt + (size_t)e * Nd * Kd;
#pragma unroll
    for (int r = 0; r < 4; r++) {
        int k = k0 + threadIdx.y + r * 8;
        t[threadIdx.y + r * 8][threadIdx.x] = Wb[(size_t)k * Nd + n0 + threadIdx.x];
    }
    __syncthreads();
    int sig = k0 + SIGMA((int)threadIdx.x);
#pragma unroll
    for (int r = 0; r < 4; r++) {
        int n = n0 + threadIdx.y + r * 8;
        Wtb[(size_t)n * Kd + sig] = f2tf_f(t[threadIdx.x][threadIdx.y + r * 8]);
    }
}

// ---------------- mma.sync tf32 grouped GEMM (128x256 CTA, 64x64 warps) -----
#define A_ROWS 128
#define B_ROWS 256
#define ROW_F  36                              // 32 data + 4 pad floats
#define STAGE_F ((A_ROWS + B_ROWS) * ROW_F)    // 13824 floats
#define B_OFF_F (A_ROWS * ROW_F)               // 4608
#define GEMM_SMEM (2 * STAGE_F * 4)            // 110592 B

template <int KTOT, int NTOT, bool G2>
__global__ __launch_bounds__(256, 1) void gemm_mma(
    const float* __restrict__ Wt, const float* __restrict__ bias,
    float* __restrict__ outp)
{
    const int e = blockIdx.z;
    const int cnt = g_count[e];
    const int m_base = blockIdx.y * 128;
    if (m_base >= cnt) return;
    const int n_base = blockIdx.x * 256;
    const int tid = threadIdx.x;
    const int lane = tid & 31;
    const int wid = tid >> 5;
    const int wm = wid >> 2;      // 0..1
    const int wn = wid & 3;       // 0..3
    const int qr = lane >> 2;     // 0..7
    const int qc = lane & 3;      // 0..3

    extern __shared__ __align__(16) float smem[];
    const uint32_t sbase = smem_u32(smem);

    // loaders: thread covers rows i*32 + (tid>>3), 16B chunk (tid&7)
    const int rloc = tid >> 3;
    const int coff = (tid & 7) * 4;           // float offset within 32-chunk
    const float* aptr[4];
#pragma unroll
    for (int i = 0; i < 4; i++) {
        int r = i * 32 + rloc;
        if (G2) {
            aptr[i] = g_hidden + (size_t)(g_off[e] + m_base + r) * KTOT + coff;
        } else {
            int am = m_base + r; if (am > cnt - 1) am = cnt - 1;
            aptr[i] = g_xr + (size_t)g_list[e][am] * KTOT + coff;
        }
    }
    const float* bbase = Wt + ((size_t)e * NTOT + n_base + rloc) * KTOT + coff;

    auto issue = [&](int c) {
        uint32_t st = sbase + (uint32_t)((c & 1) * (STAGE_F * 4));
        int k0 = c * 32;
        uint32_t ad = st + (uint32_t)(rloc * (ROW_F * 4) + coff * 4);
#pragma unroll
        for (int i = 0; i < 4; i++)
            cpa16(ad + i * 32 * (ROW_F * 4), aptr[i] + k0);
        uint32_t bd = st + (uint32_t)(B_OFF_F * 4 + rloc * (ROW_F * 4) + coff * 4);
        const float* bg = bbase + k0;
#pragma unroll
        for (int i = 0; i < 8; i++)
            cpa16(bd + i * 32 * (ROW_F * 4), bg + (size_t)i * 32 * KTOT);
    };

    float acc[4][8][4];
#pragma unroll
    for (int mi = 0; mi < 4; mi++)
#pragma unroll
        for (int nj = 0; nj < 8; nj++)
#pragma unroll
            for (int q = 0; q < 4; q++) acc[mi][nj][q] = 0.f;

    constexpr int NS = KTOT / 32;
    issue(0);
    asm volatile("cp.async.commit_group;\n" ::);
    issue(1);
    asm volatile("cp.async.commit_group;\n" ::);

    for (int c = 0; c < NS; c++) {
        // commit happens ONLY when a stage is issued; tail uses wait_group 0
        if (c + 1 < NS) {
            asm volatile("cp.async.wait_group 1;\n" ::);
        } else {
            asm volatile("cp.async.wait_group 0;\n" ::);
        }
        __syncthreads();
        const float* Sb = smem + (c & 1) * STAGE_F;
#pragma unroll
        for (int kp = 0; kp < 2; kp++) {
            float4 av[4][2];
            float4 bv[8];
#pragma unroll
            for (int mi = 0; mi < 4; mi++) {
                int r0 = wm * 64 + mi * 16 + qr;
                av[mi][0] = *reinterpret_cast<const float4*>(
                    Sb + r0 * ROW_F + qc * 8 + kp * 4);
                av[mi][1] = *reinterpret_cast<const float4*>(
                    Sb + (r0 + 8) * ROW_F + qc * 8 + kp * 4);
            }
#pragma unroll
            for (int nj = 0; nj < 8; nj++) {
                int nr = wn * 64 + nj * 8 + qr;
                bv[nj] = *reinterpret_cast<const float4*>(
                    Sb + B_OFF_F + nr * ROW_F + qc * 8 + kp * 4);
            }
#pragma unroll
            for (int mi = 0; mi < 4; mi++)
#pragma unroll
                for (int nj = 0; nj < 8; nj++) {
                    mma_tf32x(acc[mi][nj],
                              av[mi][0].x, av[mi][1].x, av[mi][0].y, av[mi][1].y,
                              bv[nj].x, bv[nj].y);
                    mma_tf32x(acc[mi][nj],
                              av[mi][0].z, av[mi][1].z, av[mi][0].w, av[mi][1].w,
                              bv[nj].z, bv[nj].w);
                }
        }
        __syncthreads();
        if (c + 2 < NS) {
            issue(c + 2);
            asm volatile("cp.async.commit_group;\n" ::);
        }
    }

    // ---- epilogue ----
    const int goff = g_off[e];
#pragma unroll
    for (int mi = 0; mi < 4; mi++) {
#pragma unroll
        for (int half = 0; half < 2; half++) {
            int rl = wm * 64 + mi * 16 + qr + half * 8;
            int gm = m_base + rl;
            if (gm >= cnt) continue;
            if (!G2) {
                float* hrow = g_hidden + (size_t)(goff + gm) * NTOT;
#pragma unroll
                for (int nj = 0; nj < 8; nj++) {
                    int col = n_base + wn * 64 + nj * 8 + qc * 2;
                    float2 bb = *reinterpret_cast<const float2*>(
                        bias + (size_t)e * NTOT + col);
                    float v0 = fmaxf(acc[mi][nj][half * 2 + 0] + bb.x, 0.f);
                    float v1 = fmaxf(acc[mi][nj][half * 2 + 1] + bb.y, 0.f);
                    int cb = col & ~31;
                    int w = col & 31;
                    hrow[cb + SIGMA(w)]     = f2tf_f(v0);
                    hrow[cb + SIGMA(w + 1)] = f2tf_f(v1);
                }
            } else {
                int t = g_list[e][gm];
                float wf = g_wlist[e][gm];
                float* orow = outp + (size_t)t * NTOT;
#pragma unroll
                for (int nj = 0; nj < 8; nj++) {
                    int col = n_base + wn * 64 + nj * 8 + qc * 2;
                    float2 bb = *reinterpret_cast<const float2*>(
                        bias + (size_t)e * NTOT + col);
                    atomicAdd(&orow[col],     wf * (acc[mi][nj][half * 2 + 0] + bb.x));
                    atomicAdd(&orow[col + 1], wf * (acc[mi][nj][half * 2 + 1] + bb.y));
                }
            }
        }
    }
}

// ---------------- launch -----------------------------------------------------
extern "C" void kernel_launch(void* const* d_in, const int* in_sizes, int n_in,
                              void* d_out, int out_size) {
    const float* x  = (const float*)d_in[0];
    const float* gw = (const float*)d_in[1];
    const float* gb = (const float*)d_in[2];
    const float* W1 = (const float*)d_in[3];
    const float* b1 = (const float*)d_in[4];
    const float* W2 = (const float*)d_in[5];
    const float* b2 = (const float*)d_in[6];
    float* out = (float*)d_out;

    void* cnt_ptr = nullptr;
    cudaGetSymbolAddress(&cnt_ptr, g_count);
    cudaMemsetAsync(cnt_ptr, 0, sizeof(int) * NE);
    cudaMemsetAsync(d_out, 0, (size_t)out_size * sizeof(float));

    gate_kernel<<<TOK / 8, 256>>>(x, gw, gb);
    offs_kernel<<<1, 1>>>();
    round_x_kernel<<<2048, 256>>>(reinterpret_cast<const float4*>(x));
    transpose_w<<<dim3(HID / 32, DID / 32, NE), dim3(32, 8)>>>(W1, g_wt1, DID, HID);
    transpose_w<<<dim3(DID / 32, HID / 32, NE), dim3(32, 8)>>>(W2, g_wt2, HID, DID);

    cudaFuncSetAttribute((const void*)gemm_mma<DID, HID, false>,
                         cudaFuncAttributeMaxDynamicSharedMemorySize, GEMM_SMEM);
    cudaFuncSetAttribute((const void*)gemm_mma<HID, DID, true>,
                         cudaFuncAttributeMaxDynamicSharedMemorySize, GEMM_SMEM);

    // GEMM1: gathered x @ W1^T -> relu -> hidden (interleaved)
    gemm_mma<DID, HID, false><<<dim3(HID / 256, TOK / 128, NE), 256, GEMM_SMEM>>>(
        g_wt1, b1, nullptr);
    // GEMM2: hidden @ W2^T -> +b2 -> weighted scatter-add
    gemm_mma<HID, DID, true><<<dim3(DID / 256, TOK / 128, NE), 256, GEMM_SMEM>>>(
        g_wt2, b2, out);
}

// round 6
// speedup vs baseline: 1.0035x; 1.0035x over previous
#include <cuda_runtime.h>
#include <cstdint>

#define TOK 16384
#define DID 1024
#define HID 4096
#define NE  8

// k-interleave within each 32-chunk: slot = (k%4)*8 + k/4
#define SIGMA(t) ((((t) & 3) << 3) | ((t) >> 2))

// ---------------- scratch ---------------------------------------------------
__device__ int   g_count[NE];
__device__ int   g_off[NE];                       // 128-aligned cumulative
__device__ __align__(16) int   g_list[NE][TOK];
__device__ __align__(16) float g_wlist[NE][TOK];
__device__ __align__(256) float g_xr[(size_t)TOK * DID];         // rounded+interleaved x
__device__ __align__(256) float g_wt1[(size_t)NE * HID * DID];   // W1^T [e][n][k]
__device__ __align__(256) float g_wt2[(size_t)NE * DID * HID];   // W2^T [e][n][k]
__device__ __align__(256) float g_hidden[(size_t)(2 * TOK + NE * 128) * HID];

// ---------------- helpers ---------------------------------------------------
__device__ __forceinline__ float f2tf_f(float f) {
    uint32_t r;
    asm("cvt.rna.tf32.f32 %0, %1;" : "=r"(r) : "f"(f));
    return __uint_as_float(r);
}
__device__ __forceinline__ uint32_t smem_u32(const void* p) {
    uint32_t a;
    asm("{ .reg .u64 t; cvta.to.shared.u64 t, %1; cvt.u32.u64 %0, t; }" : "=r"(a) : "l"(p));
    return a;
}
__device__ __forceinline__ void cpa16(uint32_t s, const void* g) {
    asm volatile("cp.async.cg.shared.global [%0], [%1], 16;\n" ::"r"(s), "l"(g));
}
__device__ __forceinline__ void mma_tf32x(float* c, float a0, float a1, float a2,
                                          float a3, float b0, float b1) {
    asm volatile(
        "mma.sync.aligned.m16n8k8.row.col.f32.tf32.tf32.f32 "
        "{%0,%1,%2,%3},{%4,%5,%6,%7},{%8,%9},{%0,%1,%2,%3};"
        : "+f"(c[0]), "+f"(c[1]), "+f"(c[2]), "+f"(c[3])
        : "r"(__float_as_uint(a0)), "r"(__float_as_uint(a1)),
          "r"(__float_as_uint(a2)), "r"(__float_as_uint(a3)),
          "r"(__float_as_uint(b0)), "r"(__float_as_uint(b1)));
}

// ---------------- gate ------------------------------------------------------
__global__ void gate_kernel(const float* __restrict__ x,
                            const float* __restrict__ gw,
                            const float* __restrict__ gb) {
    int warp = (blockIdx.x * blockDim.x + threadIdx.x) >> 5;
    int lane = threadIdx.x & 31;
    if (warp >= TOK) return;
    const float* xr = x + (size_t)warp * DID;
    float p[NE];
#pragma unroll
    for (int e = 0; e < NE; e++) p[e] = 0.f;
#pragma unroll 4
    for (int i = 0; i < DID / 32; i++) {
        int d = i * 32 + lane;
        float xv = xr[d];
        const float4* g4 = reinterpret_cast<const float4*>(gw + (size_t)d * NE);
        float4 g0 = g4[0], g1 = g4[1];
        p[0] += xv * g0.x; p[1] += xv * g0.y; p[2] += xv * g0.z; p[3] += xv * g0.w;
        p[4] += xv * g1.x; p[5] += xv * g1.y; p[6] += xv * g1.z; p[7] += xv * g1.w;
    }
#pragma unroll
    for (int e = 0; e < NE; e++)
#pragma unroll
        for (int o = 16; o > 0; o >>= 1) p[e] += __shfl_xor_sync(0xffffffffu, p[e], o);
    if (lane == 0) {
        float l[NE];
#pragma unroll
        for (int e = 0; e < NE; e++) l[e] = p[e] + gb[e];
        int e0 = 0, e1 = -1;
        float b0 = l[0], b1 = -3.0e38f;
#pragma unroll
        for (int e = 1; e < NE; e++) {
            float v = l[e];
            if (v > b0)      { b1 = b0; e1 = e0; b0 = v; e0 = e; }
            else if (v > b1) { b1 = v;  e1 = e; }
        }
        float ex = expf(b1 - b0);
        float inv = 1.f / (1.f + ex);
        int p0 = atomicAdd(&g_count[e0], 1);
        g_list[e0][p0] = warp; g_wlist[e0][p0] = inv;
        int p1 = atomicAdd(&g_count[e1], 1);
        g_list[e1][p1] = warp; g_wlist[e1][p1] = ex * inv;
    }
}

__global__ void offs_kernel() {
    int s = 0;
#pragma unroll
    for (int e = 0; e < NE; e++) { g_off[e] = s; s += (g_count[e] + 127) & ~127; }
}

// ---------------- pre-passes ------------------------------------------------
// x -> tf32-rounded, k-interleaved per 32-chunk
__global__ void round_x_kernel(const float4* __restrict__ in) {
    int n4 = TOK * DID / 4;
    for (int i = blockIdx.x * blockDim.x + threadIdx.x; i < n4;
         i += gridDim.x * blockDim.x) {
        float4 v = in[i];
        int base = (i << 2) & ~31;
        int t = i & 7;                       // SIGMA(4t+j) = j*8+t
        g_xr[base + t]      = f2tf_f(v.x);
        g_xr[base + 8 + t]  = f2tf_f(v.y);
        g_xr[base + 16 + t] = f2tf_f(v.z);
        g_xr[base + 24 + t] = f2tf_f(v.w);
    }
}

// W [e][Kd][Nd] -> Wt [e][Nd][Kd], rounded + k-interleaved.
// Tile: 128 k-rows x 32 n-cols; 16 outstanding loads/thread.
__global__ __launch_bounds__(256) void transpose_w(
    const float* __restrict__ W, float* __restrict__ Wt, int Kd, int Nd) {
    __shared__ float t[128][33];
    int e = blockIdx.z;
    int n0 = blockIdx.x * 32, k0 = blockIdx.y * 128;
    const float* Wb = W + (size_t)e * Kd * Nd;
    float* Wtb = Wt + (size_t)e * Nd * Kd;
    int tx = threadIdx.x, ty = threadIdx.y;   // (32, 8)
#pragma unroll
    for (int r = 0; r < 16; r++) {
        int k = ty + r * 8;
        t[k][tx] = Wb[(size_t)(k0 + k) * Nd + n0 + tx];
    }
    __syncthreads();
    int kin = ((tx & 7) << 2) + (tx >> 3);    // inv-sigma(tx)
#pragma unroll
    for (int r = 0; r < 4; r++) {
        int n = ty + r * 8;
        float* dst = Wtb + (size_t)(n0 + n) * Kd + k0;
#pragma unroll
        for (int c = 0; c < 4; c++)
            dst[c * 32 + tx] = f2tf_f(t[c * 32 + kin][n]);
    }
}

// ---------------- mma.sync tf32 grouped GEMM (128x128 CTA, 64x32 warps) -----
#define ROW_F  36                              // 32 data + 4 pad floats
#define STAGE_F (256 * ROW_F)                  // A 128 rows + B 128 rows
#define B_OFF_F (128 * ROW_F)
#define GEMM_SMEM (2 * STAGE_F * 4)            // 73728 B

template <int KTOT, int NTOT, bool G2>
__global__ __launch_bounds__(256, 2) void gemm_mma(
    const float* __restrict__ Wt, const float* __restrict__ bias,
    float* __restrict__ outp)
{
    const int e = blockIdx.z;
    const int cnt = g_count[e];
    const int m_base = blockIdx.y * 128;
    if (m_base >= cnt) return;
    const int n_base = blockIdx.x * 128;
    const int tid = threadIdx.x;
    const int lane = tid & 31;
    const int wid = tid >> 5;
    const int wm = wid >> 2;      // 0..1 -> 64 rows
    const int wn = wid & 3;       // 0..3 -> 32 cols
    const int qr = lane >> 2;     // 0..7
    const int qc = lane & 3;      // 0..3

    extern __shared__ __align__(16) float smem[];
    const uint32_t sbase = smem_u32(smem);

    // loaders: thread covers rows i*32 + (tid>>3), 16B chunk (tid&7); A and B
    const int rloc = tid >> 3;
    const int coff = (tid & 7) * 4;
    const float* aptr[4];
#pragma unroll
    for (int i = 0; i < 4; i++) {
        int r = i * 32 + rloc;
        if (G2) {
            aptr[i] = g_hidden + (size_t)(g_off[e] + m_base + r) * KTOT + coff;
        } else {
            int am = m_base + r; if (am > cnt - 1) am = cnt - 1;
            aptr[i] = g_xr + (size_t)g_list[e][am] * KTOT + coff;
        }
    }
    const float* bbase = Wt + ((size_t)e * NTOT + n_base + rloc) * KTOT + coff;

    auto issue = [&](int c) {
        uint32_t st = sbase + (uint32_t)((c & 1) * (STAGE_F * 4));
        int k0 = c * 32;
        uint32_t ad = st + (uint32_t)(rloc * (ROW_F * 4) + coff * 4);
#pragma unroll
        for (int i = 0; i < 4; i++)
            cpa16(ad + i * 32 * (ROW_F * 4), aptr[i] + k0);
        uint32_t bd = st + (uint32_t)(B_OFF_F * 4 + rloc * (ROW_F * 4) + coff * 4);
        const float* bg = bbase + k0;
#pragma unroll
        for (int i = 0; i < 4; i++)
            cpa16(bd + i * 32 * (ROW_F * 4), bg + (size_t)i * 32 * KTOT);
    };

    float acc[4][4][4];
#pragma unroll
    for (int mi = 0; mi < 4; mi++)
#pragma unroll
        for (int nj = 0; nj < 4; nj++)
#pragma unroll
            for (int q = 0; q < 4; q++) acc[mi][nj][q] = 0.f;

    constexpr int NS = KTOT / 32;
    issue(0);
    asm volatile("cp.async.commit_group;\n" ::);
    issue(1);
    asm volatile("cp.async.commit_group;\n" ::);

    for (int c = 0; c < NS; c++) {
        if (c + 1 < NS) {
            asm volatile("cp.async.wait_group 1;\n" ::);
        } else {
            asm volatile("cp.async.wait_group 0;\n" ::);
        }
        __syncthreads();
        const float* Sb = smem + (c & 1) * STAGE_F;
#pragma unroll
        for (int kp = 0; kp < 2; kp++) {
            float4 av[4][2];
#pragma unroll
            for (int mi = 0; mi < 4; mi++) {
                int r0 = wm * 64 + mi * 16 + qr;
                av[mi][0] = *reinterpret_cast<const float4*>(
                    Sb + r0 * ROW_F + qc * 8 + kp * 4);
                av[mi][1] = *reinterpret_cast<const float4*>(
                    Sb + (r0 + 8) * ROW_F + qc * 8 + kp * 4);
            }
#pragma unroll
            for (int nj = 0; nj < 4; nj++) {
                int nr = wn * 32 + nj * 8 + qr;
                float4 bv = *reinterpret_cast<const float4*>(
                    Sb + B_OFF_F + nr * ROW_F + qc * 8 + kp * 4);
#pragma unroll
                for (int mi = 0; mi < 4; mi++) {
                    mma_tf32x(acc[mi][nj],
                              av[mi][0].x, av[mi][1].x, av[mi][0].y, av[mi][1].y,
                              bv.x, bv.y);
                    mma_tf32x(acc[mi][nj],
                              av[mi][0].z, av[mi][1].z, av[mi][0].w, av[mi][1].w,
                              bv.z, bv.w);
                }
            }
        }
        __syncthreads();
        if (c + 2 < NS) {
            issue(c + 2);
            asm volatile("cp.async.commit_group;\n" ::);
        }
    }

    // ---- epilogue ----
    const int goff = g_off[e];
#pragma unroll
    for (int mi = 0; mi < 4; mi++) {
#pragma unroll
        for (int half = 0; half < 2; half++) {
            int rl = wm * 64 + mi * 16 + qr + half * 8;
            int gm = m_base + rl;
            if (gm >= cnt) continue;
            if (!G2) {
                float* hrow = g_hidden + (size_t)(goff + gm) * NTOT;
#pragma unroll
                for (int nj = 0; nj < 4; nj++) {
                    int col = n_base + wn * 32 + nj * 8 + qc * 2;
                    float2 bb = *reinterpret_cast<const float2*>(
                        bias + (size_t)e * NTOT + col);
                    float v0 = fmaxf(acc[mi][nj][half * 2 + 0] + bb.x, 0.f);
                    float v1 = fmaxf(acc[mi][nj][half * 2 + 1] + bb.y, 0.f);
                    int cb = col & ~31;
                    int w = col & 31;
                    hrow[cb + SIGMA(w)]     = f2tf_f(v0);
                    hrow[cb + SIGMA(w + 1)] = f2tf_f(v1);
                }
            } else {
                int t = g_list[e][gm];
                float wf = g_wlist[e][gm];
                float* orow = outp + (size_t)t * NTOT;
#pragma unroll
                for (int nj = 0; nj < 4; nj++) {
                    int col = n_base + wn * 32 + nj * 8 + qc * 2;
                    float2 bb = *reinterpret_cast<const float2*>(
                        bias + (size_t)e * NTOT + col);
                    atomicAdd(&orow[col],     wf * (acc[mi][nj][half * 2 + 0] + bb.x));
                    atomicAdd(&orow[col + 1], wf * (acc[mi][nj][half * 2 + 1] + bb.y));
                }
            }
        }
    }
}

// ---------------- launch -----------------------------------------------------
extern "C" void kernel_launch(void* const* d_in, const int* in_sizes, int n_in,
                              void* d_out, int out_size) {
    const float* x  = (const float*)d_in[0];
    const float* gw = (const float*)d_in[1];
    const float* gb = (const float*)d_in[2];
    const float* W1 = (const float*)d_in[3];
    const float* b1 = (const float*)d_in[4];
    const float* W2 = (const float*)d_in[5];
    const float* b2 = (const float*)d_in[6];
    float* out = (float*)d_out;

    void* cnt_ptr = nullptr;
    cudaGetSymbolAddress(&cnt_ptr, g_count);
    cudaMemsetAsync(cnt_ptr, 0, sizeof(int) * NE);
    cudaMemsetAsync(d_out, 0, (size_t)out_size * sizeof(float));

    gate_kernel<<<TOK / 8, 256>>>(x, gw, gb);
    offs_kernel<<<1, 1>>>();
    round_x_kernel<<<2048, 256>>>(reinterpret_cast<const float4*>(x));
    transpose_w<<<dim3(HID / 32, DID / 128, NE), dim3(32, 8)>>>(W1, g_wt1, DID, HID);
    transpose_w<<<dim3(DID / 32, HID / 128, NE), dim3(32, 8)>>>(W2, g_wt2, HID, DID);

    cudaFuncSetAttribute((const void*)gemm_mma<DID, HID, false>,
                         cudaFuncAttributeMaxDynamicSharedMemorySize, GEMM_SMEM);
    cudaFuncSetAttribute((const void*)gemm_mma<HID, DID, true>,
                         cudaFuncAttributeMaxDynamicSharedMemorySize, GEMM_SMEM);

    // GEMM1: gathered x @ W1^T -> relu -> hidden (interleaved)
    gemm_mma<DID, HID, false><<<dim3(HID / 128, TOK / 128, NE), 256, GEMM_SMEM>>>(
        g_wt1, b1, nullptr);
    // GEMM2: hidden @ W2^T -> +b2 -> weighted scatter-add
    gemm_mma<HID, DID, true><<<dim3(DID / 128, TOK / 128, NE), 256, GEMM_SMEM>>>(
        g_wt2, b2, out);
}

// round 9
// speedup vs baseline: 12.2896x; 12.2470x over previous
#include <cuda_runtime.h>
#include <cstdint>

#define TOK 16384
#define DID 1024
#define HID 4096
#define NE  8

// sigma k-interleave within a 32-float chunk: slot = (k%4)*8 + k/4
// inverse: k = (s%8)*4 + s/8
#define SINV(s) ((((s) & 7) << 2) | ((s) >> 3))

// ---------------- scratch (kept ~514MB total: R1-proven device-resident) ----
__device__ int   g_count[NE];
__device__ int   g_off[NE];
__device__ __align__(16) int   g_list[NE][TOK];
__device__ __align__(16) float g_wlist[NE][TOK];
__device__ __align__(256) float g_hidden[(size_t)(2 * TOK + 128) * HID]; // 514MB

// ---------------- helpers ---------------------------------------------------
__device__ __forceinline__ float f2tf_f(float f) {
    uint32_t r;
    asm("cvt.rna.tf32.f32 %0, %1;" : "=r"(r) : "f"(f));
    return __uint_as_float(r);
}
__device__ __forceinline__ uint32_t smem_u32(const void* p) {
    uint32_t a;
    asm("{ .reg .u64 t; cvta.to.shared.u64 t, %1; cvt.u32.u64 %0, t; }" : "=r"(a) : "l"(p));
    return a;
}
__device__ __forceinline__ void cpa16(uint32_t s, const void* g) {
    asm volatile("cp.async.cg.shared.global [%0], [%1], 16;\n" ::"r"(s), "l"(g));
}
__device__ __forceinline__ void mma_tf32x(float* c, float a0, float a1, float a2,
                                          float a3, float b0, float b1) {
    asm volatile(
        "mma.sync.aligned.m16n8k8.row.col.f32.tf32.tf32.f32 "
        "{%0,%1,%2,%3},{%4,%5,%6,%7},{%8,%9},{%0,%1,%2,%3};"
        : "+f"(c[0]), "+f"(c[1]), "+f"(c[2]), "+f"(c[3])
        : "r"(__float_as_uint(a0)), "r"(__float_as_uint(a1)),
          "r"(__float_as_uint(a2)), "r"(__float_as_uint(a3)),
          "r"(__float_as_uint(b0)), "r"(__float_as_uint(b1)));
}

// ---------------- gate ------------------------------------------------------
__global__ void gate_kernel(const float* __restrict__ x,
                            const float* __restrict__ gw,
                            const float* __restrict__ gb) {
    int warp = (blockIdx.x * blockDim.x + threadIdx.x) >> 5;
    int lane = threadIdx.x & 31;
    if (warp >= TOK) return;
    const float* xr = x + (size_t)warp * DID;
    float p[NE];
#pragma unroll
    for (int e = 0; e < NE; e++) p[e] = 0.f;
#pragma unroll 4
    for (int i = 0; i < DID / 32; i++) {
        int d = i * 32 + lane;
        float xv = xr[d];
        const float4* g4 = reinterpret_cast<const float4*>(gw + (size_t)d * NE);
        float4 g0 = g4[0], g1 = g4[1];
        p[0] += xv * g0.x; p[1] += xv * g0.y; p[2] += xv * g0.z; p[3] += xv * g0.w;
        p[4] += xv * g1.x; p[5] += xv * g1.y; p[6] += xv * g1.z; p[7] += xv * g1.w;
    }
#pragma unroll
    for (int e = 0; e < NE; e++)
#pragma unroll
        for (int o = 16; o > 0; o >>= 1) p[e] += __shfl_xor_sync(0xffffffffu, p[e], o);
    if (lane == 0) {
        float l[NE];
#pragma unroll
        for (int e = 0; e < NE; e++) l[e] = p[e] + gb[e];
        int e0 = 0, e1 = -1;
        float b0 = l[0], b1 = -3.0e38f;
#pragma unroll
        for (int e = 1; e < NE; e++) {
            float v = l[e];
            if (v > b0)      { b1 = b0; e1 = e0; b0 = v; e0 = e; }
            else if (v > b1) { b1 = v;  e1 = e; }
        }
        float ex = expf(b1 - b0);
        float inv = 1.f / (1.f + ex);
        int p0 = atomicAdd(&g_count[e0], 1);
        g_list[e0][p0] = warp; g_wlist[e0][p0] = inv;
        int p1 = atomicAdd(&g_count[e1], 1);
        g_list[e1][p1] = warp; g_wlist[e1][p1] = ex * inv;
    }
}

__global__ void offs_kernel() {
    int s = 0;
#pragma unroll
    for (int e = 0; e < NE; e++) { g_off[e] = s; s += g_count[e]; }
}

// ---------------- tf32 grouped GEMM: 128x128 CTA, in-smem convert -----------
// smem layout (floats):
#define AR_STR 36
#define AR_F (128 * AR_STR)                 // 4608 (raw A, padded for banks)
#define BR_F (32 * 128)                     // 4096 (raw B)
#define BC_STR 136
#define OFF_BRAW (2 * AR_F)                 // 9216
#define OFF_ACONV (OFF_BRAW + 2 * BR_F)     // 17408
#define OFF_BCONV (OFF_ACONV + 128 * AR_STR)// 22016
#define SMEM_F (OFF_BCONV + 32 * BC_STR)    // 26368 floats
#define GEMM_SMEM (SMEM_F * 4)              // 105472 B

template <int KTOT, int NTOT, bool G2>
__global__ __launch_bounds__(256, 2) void gemm_mma(
    const float* __restrict__ Asrc,     // x for G1; unused G2
    const float* __restrict__ W,        // [E][KTOT][NTOT] native
    const float* __restrict__ bias,
    float* __restrict__ outp)
{
    const int e = blockIdx.z;
    const int cnt = g_count[e];
    const int m_base = blockIdx.y * 128;
    if (m_base >= cnt) return;
    const int n_base = blockIdx.x * 128;
    const int tid = threadIdx.x;
    const int lane = tid & 31;
    const int wid = tid >> 5;
    const int wm = wid >> 2, wn = wid & 3;
    const int qr = lane >> 2, qc = lane & 3;

    extern __shared__ __align__(16) float sm[];
    const uint32_t sb = smem_u32(sm);

    // A cp.async: 2 threads/row (ar=tid>>1), 16 floats each
    const int ar = tid >> 1, ah = tid & 1;
    const float* aptr;
    if (G2) {
        aptr = g_hidden + (size_t)(g_off[e] + m_base + ar) * KTOT + ah * 16;
    } else {
        int am = m_base + ar; if (am > cnt - 1) am = cnt - 1;
        aptr = Asrc + (size_t)g_list[e][am] * KTOT + ah * 16;
    }
    const uint32_t a_dst = (uint32_t)((ar * AR_STR + ah * 16) * 4);
    // B cp.async: 8 threads/k-row (rb=tid>>3), 16 floats each, native [K][N]
    const int rb = tid >> 3, seg = tid & 7;
    const float* bptr = W + ((size_t)e * KTOT + rb) * NTOT + n_base + seg * 16;
    const uint32_t b_dst = (uint32_t)((rb * 128 + seg * 16) * 4);

    auto issue = [&](int c) {
        int buf = c & 1;
        uint32_t ad = sb + (uint32_t)(buf * AR_F * 4) + a_dst;
        const float* ag = aptr + c * 32;
        cpa16(ad, ag); cpa16(ad + 16, ag + 4);
        cpa16(ad + 32, ag + 8); cpa16(ad + 48, ag + 12);
        uint32_t bd = sb + (uint32_t)((OFF_BRAW + buf * BR_F) * 4) + b_dst;
        const float* bg = bptr + (size_t)c * 32 * NTOT;
        cpa16(bd, bg); cpa16(bd + 16, bg + 4);          // FIX: full 16 floats,
        cpa16(bd + 32, bg + 8); cpa16(bd + 48, bg + 12); // was 1 cpa16 (1/4 tile)
    };

    float acc[4][4][4];
#pragma unroll
    for (int mi = 0; mi < 4; mi++)
#pragma unroll
        for (int nj = 0; nj < 4; nj++)
#pragma unroll
            for (int q = 0; q < 4; q++) acc[mi][nj][q] = 0.f;

    constexpr int NS = KTOT / 32;
    issue(0);
    asm volatile("cp.async.commit_group;\n" ::);
    issue(1);
    asm volatile("cp.async.commit_group;\n" ::);

    for (int c = 0; c < NS; c++) {
        if (c + 1 < NS) {
            asm volatile("cp.async.wait_group 1;\n" ::);
        } else {
            asm volatile("cp.async.wait_group 0;\n" ::);
        }
        __syncthreads();                     // S1: raw data ready, prev mainloop done

        // ---- convert pass: round to tf32 (rna); A also sigma-permuted ----
        const int abuf = c & 1;
        if (tid < 128) {
            const float* src = sm + abuf * AR_F + tid * AR_STR;
            float r[32];
#pragma unroll
            for (int u = 0; u < 8; u++) {
                float4 v = *reinterpret_cast<const float4*>(src + 4 * u);
                r[4 * u] = v.x; r[4 * u + 1] = v.y;
                r[4 * u + 2] = v.z; r[4 * u + 3] = v.w;
            }
            float* dst = sm + OFF_ACONV + tid * AR_STR;
#pragma unroll
            for (int u = 0; u < 8; u++) {
                float4 o;
                o.x = f2tf_f(r[SINV(4 * u + 0)]);
                o.y = f2tf_f(r[SINV(4 * u + 1)]);
                o.z = f2tf_f(r[SINV(4 * u + 2)]);
                o.w = f2tf_f(r[SINV(4 * u + 3)]);
                *reinterpret_cast<float4*>(dst + 4 * u) = o;
            }
        } else {
            const int t2 = tid - 128;
            const float* srcB = sm + OFF_BRAW + abuf * BR_F;
            float* dstB = sm + OFF_BCONV;
#pragma unroll
            for (int i = 0; i < 8; i++) {
                int idx = t2 + 128 * i;
                int row = idx >> 5, pos = idx & 31;
                float4 v = *reinterpret_cast<const float4*>(srcB + row * 128 + pos * 4);
                v.x = f2tf_f(v.x); v.y = f2tf_f(v.y);
                v.z = f2tf_f(v.z); v.w = f2tf_f(v.w);
                *reinterpret_cast<float4*>(dstB + row * BC_STR + pos * 4) = v;
            }
        }
        __syncthreads();                     // S2: converted tiles visible

        if (c + 2 < NS) {                    // raw bufs free now
            issue(c + 2);
            asm volatile("cp.async.commit_group;\n" ::);
        }

        // ---- mainloop: zero CVT, conflict-free LDS ----
        const float* Ac = sm + OFF_ACONV;
        const float* Bc = sm + OFF_BCONV;
#pragma unroll
        for (int kp = 0; kp < 2; kp++) {
            float4 av[4][2];
#pragma unroll
            for (int mi = 0; mi < 4; mi++) {
                int r0 = wm * 64 + mi * 16 + qr;
                av[mi][0] = *reinterpret_cast<const float4*>(
                    Ac + r0 * AR_STR + qc * 8 + kp * 4);
                av[mi][1] = *reinterpret_cast<const float4*>(
                    Ac + (r0 + 8) * AR_STR + qc * 8 + kp * 4);
            }
#pragma unroll
            for (int nj = 0; nj < 4; nj++) {
                int nc = wn * 32 + nj * 8 + qr;
                float b0 = Bc[(16 * kp + qc) * BC_STR + nc];
                float b1 = Bc[(16 * kp + 4 + qc) * BC_STR + nc];
                float b2 = Bc[(16 * kp + 8 + qc) * BC_STR + nc];
                float b3 = Bc[(16 * kp + 12 + qc) * BC_STR + nc];
#pragma unroll
                for (int mi = 0; mi < 4; mi++) {
                    mma_tf32x(acc[mi][nj],
                              av[mi][0].x, av[mi][1].x, av[mi][0].y, av[mi][1].y,
                              b0, b1);
                    mma_tf32x(acc[mi][nj],
                              av[mi][0].z, av[mi][1].z, av[mi][0].w, av[mi][1].w,
                              b2, b3);
                }
            }
        }
    }

    // ---- epilogue ----
    const int goff = g_off[e];
#pragma unroll
    for (int mi = 0; mi < 4; mi++) {
#pragma unroll
        for (int half = 0; half < 2; half++) {
            int rl = wm * 64 + mi * 16 + qr + half * 8;
            int gm = m_base + rl;
            if (gm >= cnt) continue;
            if (!G2) {
                float* hrow = g_hidden + (size_t)(goff + gm) * NTOT;
#pragma unroll
                for (int nj = 0; nj < 4; nj++) {
                    int col = n_base + wn * 32 + nj * 8 + qc * 2;
                    float2 bb = *reinterpret_cast<const float2*>(
                        bias + (size_t)e * NTOT + col);
                    float2 v;
                    v.x = fmaxf(acc[mi][nj][half * 2 + 0] + bb.x, 0.f);
                    v.y = fmaxf(acc[mi][nj][half * 2 + 1] + bb.y, 0.f);
                    *reinterpret_cast<float2*>(hrow + col) = v;   // G2 rounds later
                }
            } else {
                int t = g_list[e][gm];
                float wf = g_wlist[e][gm];
                float* orow = outp + (size_t)t * NTOT;
#pragma unroll
                for (int nj = 0; nj < 4; nj++) {
                    int col = n_base + wn * 32 + nj * 8 + qc * 2;
                    float2 bb = *reinterpret_cast<const float2*>(
                        bias + (size_t)e * NTOT + col);
                    atomicAdd(&orow[col],     wf * (acc[mi][nj][half * 2 + 0] + bb.x));
                    atomicAdd(&orow[col + 1], wf * (acc[mi][nj][half * 2 + 1] + bb.y));
                }
            }
        }
    }
}

// ---------------- launch -----------------------------------------------------
extern "C" void kernel_launch(void* const* d_in, const int* in_sizes, int n_in,
                              void* d_out, int out_size) {
    const float* x  = (const float*)d_in[0];
    const float* gw = (const float*)d_in[1];
    const float* gb = (const float*)d_in[2];
    const float* W1 = (const float*)d_in[3];
    const float* b1 = (const float*)d_in[4];
    const float* W2 = (const float*)d_in[5];
    const float* b2 = (const float*)d_in[6];
    float* out = (float*)d_out;

    void* cnt_ptr = nullptr;
    cudaGetSymbolAddress(&cnt_ptr, g_count);
    cudaMemsetAsync(cnt_ptr, 0, sizeof(int) * NE);
    cudaMemsetAsync(d_out, 0, (size_t)out_size * sizeof(float));

    gate_kernel<<<TOK / 8, 256>>>(x, gw, gb);
    offs_kernel<<<1, 1>>>();

    cudaFuncSetAttribute((const void*)gemm_mma<DID, HID, false>,
                         cudaFuncAttributeMaxDynamicSharedMemorySize, GEMM_SMEM);
    cudaFuncSetAttribute((const void*)gemm_mma<HID, DID, true>,
                         cudaFuncAttributeMaxDynamicSharedMemorySize, GEMM_SMEM);

    // GEMM1: gathered x @ W1 -> relu -> hidden (plain fp32)
    gemm_mma<DID, HID, false><<<dim3(HID / 128, TOK / 128, NE), 256, GEMM_SMEM>>>(
        x, W1, b1, nullptr);
    // GEMM2: hidden @ W2 -> +b2 -> weighted atomic scatter into out
    gemm_mma<HID, DID, true><<<dim3(DID / 128, TOK / 128, NE), 256, GEMM_SMEM>>>(
        nullptr, W2, b2, out);
}

// round 13
// speedup vs baseline: 13.0650x; 1.0631x over previous
#include <cuda_runtime.h>
#include <cstdint>

#define TOK 16384
#define DID 1024
#define HID 4096
#define NE  8

// sigma k-interleave within a 32-float chunk: slot = (k%4)*8 + k/4
#define SIGMA(t) ((((t) & 3) << 3) | ((t) >> 2))

// ---------------- scratch (~603MB; referenced ONLY in device code) ----------
__device__ int   g_count[NE];
__device__ int   g_off[NE];
__device__ __align__(16) int   g_list[NE][TOK];
__device__ __align__(16) float g_wlist[NE][TOK];
__device__ __align__(256) float g_xr[(size_t)TOK * DID];                  // 64MB
__device__ __align__(256) float g_hidden[(size_t)(2 * TOK + 128) * HID];  // 539MB

// ---------------- helpers ---------------------------------------------------
__device__ __forceinline__ float f2tf_f(float f) {
    uint32_t r;
    asm("cvt.rna.tf32.f32 %0, %1;" : "=r"(r) : "f"(f));
    return __uint_as_float(r);
}
__device__ __forceinline__ uint32_t smem_u32(const void* p) {
    uint32_t a;
    asm("{ .reg .u64 t; cvta.to.shared.u64 t, %1; cvt.u32.u64 %0, t; }" : "=r"(a) : "l"(p));
    return a;
}
__device__ __forceinline__ void cpa16(uint32_t s, const void* g) {
    asm volatile("cp.async.cg.shared.global [%0], [%1], 16;\n" ::"r"(s), "l"(g));
}
__device__ __forceinline__ void mma_tf32x(float* c, float a0, float a1, float a2,
                                          float a3, float b0, float b1) {
    asm volatile(
        "mma.sync.aligned.m16n8k8.row.col.f32.tf32.tf32.f32 "
        "{%0,%1,%2,%3},{%4,%5,%6,%7},{%8,%9},{%0,%1,%2,%3};"
        : "+f"(c[0]), "+f"(c[1]), "+f"(c[2]), "+f"(c[3])
        : "r"(__float_as_uint(a0)), "r"(__float_as_uint(a1)),
          "r"(__float_as_uint(a2)), "r"(__float_as_uint(a3)),
          "r"(__float_as_uint(b0)), "r"(__float_as_uint(b1)));
}

// ---------------- gate (reads RAW x: selection identical to reference) ------
__global__ void gate_kernel(const float* __restrict__ x,
                            const float* __restrict__ gw,
                            const float* __restrict__ gb) {
    int warp = (blockIdx.x * blockDim.x + threadIdx.x) >> 5;
    int lane = threadIdx.x & 31;
    if (warp >= TOK) return;
    const float* xr = x + (size_t)warp * DID;
    float p[NE];
#pragma unroll
    for (int e = 0; e < NE; e++) p[e] = 0.f;
#pragma unroll 4
    for (int i = 0; i < DID / 32; i++) {
        int d = i * 32 + lane;
        float xv = xr[d];
        const float4* g4 = reinterpret_cast<const float4*>(gw + (size_t)d * NE);
        float4 g0 = g4[0], g1 = g4[1];
        p[0] += xv * g0.x; p[1] += xv * g0.y; p[2] += xv * g0.z; p[3] += xv * g0.w;
        p[4] += xv * g1.x; p[5] += xv * g1.y; p[6] += xv * g1.z; p[7] += xv * g1.w;
    }
#pragma unroll
    for (int e = 0; e < NE; e++)
#pragma unroll
        for (int o = 16; o > 0; o >>= 1) p[e] += __shfl_xor_sync(0xffffffffu, p[e], o);
    if (lane == 0) {
        float l[NE];
#pragma unroll
        for (int e = 0; e < NE; e++) l[e] = p[e] + gb[e];
        int e0 = 0, e1 = -1;
        float b0 = l[0], b1 = -3.0e38f;
#pragma unroll
        for (int e = 1; e < NE; e++) {
            float v = l[e];
            if (v > b0)      { b1 = b0; e1 = e0; b0 = v; e0 = e; }
            else if (v > b1) { b1 = v;  e1 = e; }
        }
        float ex = expf(b1 - b0);
        float inv = 1.f / (1.f + ex);
        int p0 = atomicAdd(&g_count[e0], 1);
        g_list[e0][p0] = warp; g_wlist[e0][p0] = inv;
        int p1 = atomicAdd(&g_count[e1], 1);
        g_list[e1][p1] = warp; g_wlist[e1][p1] = ex * inv;
    }
}

__global__ void offs_kernel() {
    int s = 0;
#pragma unroll
    for (int e = 0; e < NE; e++) { g_off[e] = s; s += g_count[e]; }
}

// ---------------- pre-pass: x -> g_xr (rounded rna + sigma-interleaved) -----
__global__ void round_x_kernel(const float4* __restrict__ in) {
    int n4 = TOK * DID / 4;
    for (int i = blockIdx.x * blockDim.x + threadIdx.x; i < n4;
         i += gridDim.x * blockDim.x) {
        float4 v = in[i];
        int base = (i << 2) & ~31;
        int t = i & 7;                       // SIGMA(4t+j) = j*8+t
        g_xr[base + t]      = f2tf_f(v.x);
        g_xr[base + 8 + t]  = f2tf_f(v.y);
        g_xr[base + 16 + t] = f2tf_f(v.z);
        g_xr[base + 24 + t] = f2tf_f(v.w);
    }
}

// ---------------- tf32 grouped GEMM: 128x128 CTA, 3-stage, 1 sync/chunk -----
#define AR_STR 36
#define B_STR  136
#define A_F    (128 * AR_STR)               // 4608 floats
#define STAGE_F (A_F + 32 * B_STR)          // 8960 floats
#define GEMM_SMEM (3 * STAGE_F * 4)         // 107520 B

template <int KTOT, int NTOT, bool G2>
__global__ __launch_bounds__(256, 2) void gemm_mma(
    const float* __restrict__ W,        // [E][KTOT][NTOT] native, UNMODIFIED
    const float* __restrict__ bias,
    float* __restrict__ outp)
{
    const int e = blockIdx.z;
    const int cnt = g_count[e];
    const int m_base = blockIdx.y * 128;
    if (m_base >= cnt) return;
    const int n_base = blockIdx.x * 128;
    const int tid = threadIdx.x;
    const int lane = tid & 31;
    const int wid = tid >> 5;
    const int wm = wid >> 2, wn = wid & 3;
    const int qr = lane >> 2, qc = lane & 3;

    extern __shared__ __align__(16) float sm[];
    const uint32_t sb = smem_u32(sm);

    // A: 2 threads/row, 16 floats each. Device-symbol sources ONLY (fix:
    // passing __device__ symbols as host-side kernel args gave a host-shadow
    // garbage pointer in R10-R12).
    const int ar = tid >> 1, ah = tid & 1;
    const float* aptr;
    if (G2) {
        aptr = g_hidden + (size_t)(g_off[e] + m_base + ar) * KTOT + ah * 16;
    } else {
        int am = m_base + ar; if (am > cnt - 1) am = cnt - 1;
        aptr = g_xr + (size_t)g_list[e][am] * KTOT + ah * 16;
    }
    const uint32_t a_dst = (uint32_t)((ar * AR_STR + ah * 16) * 4);
    // B: 8 threads/k-row, 16 floats each, native [K][N]
    const int rb = tid >> 3, seg = tid & 7;
    const float* bptr = W + ((size_t)e * KTOT + rb) * NTOT + n_base + seg * 16;
    const uint32_t b_dst = (uint32_t)((A_F + rb * B_STR + seg * 16) * 4);

    auto issue = [&](int c) {
        uint32_t st = sb + (uint32_t)((c % 3) * (STAGE_F * 4));
        const float* ag = aptr + c * 32;
        uint32_t ad = st + a_dst;
        cpa16(ad, ag); cpa16(ad + 16, ag + 4);
        cpa16(ad + 32, ag + 8); cpa16(ad + 48, ag + 12);
        const float* bg = bptr + (size_t)c * 32 * NTOT;
        uint32_t bd = st + b_dst;
        cpa16(bd, bg); cpa16(bd + 16, bg + 4);
        cpa16(bd + 32, bg + 8); cpa16(bd + 48, bg + 12);
        asm volatile("cp.async.commit_group;\n" ::);
    };

    float acc[4][4][4];
#pragma unroll
    for (int mi = 0; mi < 4; mi++)
#pragma unroll
        for (int nj = 0; nj < 4; nj++)
#pragma unroll
            for (int q = 0; q < 4; q++) acc[mi][nj][q] = 0.f;

    constexpr int NS = KTOT / 32;
    issue(0);
    issue(1);

    for (int c = 0; c < NS; c++) {
        if (c + 1 < NS) {
            asm volatile("cp.async.wait_group 1;\n" ::);
        } else {
            asm volatile("cp.async.wait_group 0;\n" ::);
        }
        __syncthreads();           // stage c visible; stage (c+2)%3 free
        if (c + 2 < NS) issue(c + 2);

        const float* Ac = sm + (c % 3) * STAGE_F;
        const float* Bc = Ac + A_F;
#pragma unroll
        for (int kp = 0; kp < 2; kp++) {
            float4 av[4][2];
#pragma unroll
            for (int mi = 0; mi < 4; mi++) {
                int r0 = wm * 64 + mi * 16 + qr;
                av[mi][0] = *reinterpret_cast<const float4*>(
                    Ac + r0 * AR_STR + qc * 8 + kp * 4);
                av[mi][1] = *reinterpret_cast<const float4*>(
                    Ac + (r0 + 8) * AR_STR + qc * 8 + kp * 4);
            }
#pragma unroll
            for (int nj = 0; nj < 4; nj++) {
                int nc = wn * 32 + nj * 8 + qr;
                // B rounded to tf32 (rna) in registers
                float b0 = f2tf_f(Bc[(16 * kp + qc) * B_STR + nc]);
                float b1 = f2tf_f(Bc[(16 * kp + 4 + qc) * B_STR + nc]);
                float b2 = f2tf_f(Bc[(16 * kp + 8 + qc) * B_STR + nc]);
                float b3 = f2tf_f(Bc[(16 * kp + 12 + qc) * B_STR + nc]);
#pragma unroll
                for (int mi = 0; mi < 4; mi++) {
                    mma_tf32x(acc[mi][nj],
                              av[mi][0].x, av[mi][1].x, av[mi][0].y, av[mi][1].y,
                              b0, b1);
                    mma_tf32x(acc[mi][nj],
                              av[mi][0].z, av[mi][1].z, av[mi][0].w, av[mi][1].w,
                              b2, b3);
                }
            }
        }
    }

    // ---- epilogue ----
    const int goff = g_off[e];
#pragma unroll
    for (int mi = 0; mi < 4; mi++) {
#pragma unroll
        for (int half = 0; half < 2; half++) {
            int rl = wm * 64 + mi * 16 + qr + half * 8;
            int gm = m_base + rl;
            if (gm >= cnt) continue;
            if (!G2) {
                // hidden written sigma-interleaved + tf32-rounded:
                // GEMM2 consumes it with zero A-side conversion
                float* hrow = g_hidden + (size_t)(goff + gm) * NTOT;
#pragma unroll
                for (int nj = 0; nj < 4; nj++) {
                    int col = n_base + wn * 32 + nj * 8 + qc * 2;
                    float2 bb = *reinterpret_cast<const float2*>(
                        bias + (size_t)e * NTOT + col);
                    float v0 = fmaxf(acc[mi][nj][half * 2 + 0] + bb.x, 0.f);
                    float v1 = fmaxf(acc[mi][nj][half * 2 + 1] + bb.y, 0.f);
                    int cb = col & ~31;
                    int w = col & 31;
                    hrow[cb + SIGMA(w)]     = f2tf_f(v0);
                    hrow[cb + SIGMA(w + 1)] = f2tf_f(v1);
                }
            } else {
                int t = g_list[e][gm];
                float wf = g_wlist[e][gm];
                float* orow = outp + (size_t)t * NTOT;
#pragma unroll
                for (int nj = 0; nj < 4; nj++) {
                    int col = n_base + wn * 32 + nj * 8 + qc * 2;
                    float2 bb = *reinterpret_cast<const float2*>(
                        bias + (size_t)e * NTOT + col);
                    atomicAdd(&orow[col],     wf * (acc[mi][nj][half * 2 + 0] + bb.x));
                    atomicAdd(&orow[col + 1], wf * (acc[mi][nj][half * 2 + 1] + bb.y));
                }
            }
        }
    }
}

// ---------------- launch -----------------------------------------------------
extern "C" void kernel_launch(void* const* d_in, const int* in_sizes, int n_in,
                              void* d_out, int out_size) {
    const float* x  = (const float*)d_in[0];
    const float* gw = (const float*)d_in[1];
    const float* gb = (const float*)d_in[2];
    const float* W1 = (const float*)d_in[3];   // never modified
    const float* b1 = (const float*)d_in[4];
    const float* W2 = (const float*)d_in[5];   // never modified
    const float* b2 = (const float*)d_in[6];
    float* out = (float*)d_out;

    void* cnt_ptr = nullptr;
    cudaGetSymbolAddress(&cnt_ptr, g_count);
    cudaMemsetAsync(cnt_ptr, 0, sizeof(int) * NE);
    cudaMemsetAsync(d_out, 0, (size_t)out_size * sizeof(float));

    gate_kernel<<<TOK / 8, 256>>>(x, gw, gb);   // gate uses RAW x
    offs_kernel<<<1, 1>>>();
    round_x_kernel<<<2048, 256>>>(reinterpret_cast<const float4*>(x));

    cudaFuncSetAttribute((const void*)gemm_mma<DID, HID, false>,
                         cudaFuncAttributeMaxDynamicSharedMemorySize, GEMM_SMEM);
    cudaFuncSetAttribute((const void*)gemm_mma<HID, DID, true>,
                         cudaFuncAttributeMaxDynamicSharedMemorySize, GEMM_SMEM);

    // GEMM1: gathered g_xr (device symbol, read in-kernel) @ W1 -> relu -> hidden
    gemm_mma<DID, HID, false><<<dim3(HID / 128, TOK / 128, NE), 256, GEMM_SMEM>>>(
        W1, b1, nullptr);
    // GEMM2: hidden @ W2 -> +b2 -> weighted atomic scatter into out
    gemm_mma<HID, DID, true><<<dim3(DID / 128, TOK / 128, NE), 256, GEMM_SMEM>>>(
        W2, b2, out);
}

// round 15
// speedup vs baseline: 13.3339x; 1.0206x over previous
#include <cuda_runtime.h>
#include <cstdint>

#define TOK 16384
#define DID 1024
#define HID 4096
#define NE  8

// sigma k-interleave within a 32-float chunk: slot s holds k = SINV(s)
#define SINV(s) ((((s) & 7) << 2) | ((s) >> 3))
#define SIGMA(t) ((((t) & 3) << 3) | ((t) >> 2))

// ------ scratch (~859MB; symbols referenced ONLY inside device code) --------
__device__ int   g_count[NE];
__device__ int   g_off[NE];
__device__ __align__(16) int   g_list[NE][TOK];
__device__ __align__(16) float g_wlist[NE][TOK];
__device__ __align__(256) float g_xr[(size_t)TOK * DID];                  // 64MB
__device__ __align__(256) float g_wt1[(size_t)NE * HID * DID];            // 128MB
__device__ __align__(256) float g_wt2[(size_t)NE * DID * HID];            // 128MB
__device__ __align__(256) float g_hidden[(size_t)(2 * TOK + 128) * HID];  // 539MB

// ---------------- helpers ---------------------------------------------------
__device__ __forceinline__ float f2tf_f(float f) {
    uint32_t r;
    asm("cvt.rna.tf32.f32 %0, %1;" : "=r"(r) : "f"(f));
    return __uint_as_float(r);
}
__device__ __forceinline__ uint32_t smem_u32(const void* p) {
    uint32_t a;
    asm("{ .reg .u64 t; cvta.to.shared.u64 t, %1; cvt.u32.u64 %0, t; }" : "=r"(a) : "l"(p));
    return a;
}
__device__ __forceinline__ void cpa16(uint32_t s, const void* g) {
    asm volatile("cp.async.cg.shared.global [%0], [%1], 16;\n" ::"r"(s), "l"(g));
}
__device__ __forceinline__ void mma_tf32x(float* c, float a0, float a1, float a2,
                                          float a3, float b0, float b1) {
    asm volatile(
        "mma.sync.aligned.m16n8k8.row.col.f32.tf32.tf32.f32 "
        "{%0,%1,%2,%3},{%4,%5,%6,%7},{%8,%9},{%0,%1,%2,%3};"
        : "+f"(c[0]), "+f"(c[1]), "+f"(c[2]), "+f"(c[3])
        : "r"(__float_as_uint(a0)), "r"(__float_as_uint(a1)),
          "r"(__float_as_uint(a2)), "r"(__float_as_uint(a3)),
          "r"(__float_as_uint(b0)), "r"(__float_as_uint(b1)));
}

// ---------------- gate (RAW x: selection identical to reference) ------------
__global__ void gate_kernel(const float* __restrict__ x,
                            const float* __restrict__ gw,
                            const float* __restrict__ gb) {
    int warp = (blockIdx.x * blockDim.x + threadIdx.x) >> 5;
    int lane = threadIdx.x & 31;
    if (warp >= TOK) return;
    const float* xr = x + (size_t)warp * DID;
    float p[NE];
#pragma unroll
    for (int e = 0; e < NE; e++) p[e] = 0.f;
#pragma unroll 4
    for (int i = 0; i < DID / 32; i++) {
        int d = i * 32 + lane;
        float xv = xr[d];
        const float4* g4 = reinterpret_cast<const float4*>(gw + (size_t)d * NE);
        float4 g0 = g4[0], g1 = g4[1];
        p[0] += xv * g0.x; p[1] += xv * g0.y; p[2] += xv * g0.z; p[3] += xv * g0.w;
        p[4] += xv * g1.x; p[5] += xv * g1.y; p[6] += xv * g1.z; p[7] += xv * g1.w;
    }
#pragma unroll
    for (int e = 0; e < NE; e++)
#pragma unroll
        for (int o = 16; o > 0; o >>= 1) p[e] += __shfl_xor_sync(0xffffffffu, p[e], o);
    if (lane == 0) {
        float l[NE];
#pragma unroll
        for (int e = 0; e < NE; e++) l[e] = p[e] + gb[e];
        int e0 = 0, e1 = -1;
        float b0 = l[0], b1 = -3.0e38f;
#pragma unroll
        for (int e = 1; e < NE; e++) {
            float v = l[e];
            if (v > b0)      { b1 = b0; e1 = e0; b0 = v; e0 = e; }
            else if (v > b1) { b1 = v;  e1 = e; }
        }
        float ex = expf(b1 - b0);
        float inv = 1.f / (1.f + ex);
        int p0 = atomicAdd(&g_count[e0], 1);
        g_list[e0][p0] = warp; g_wlist[e0][p0] = inv;
        int p1 = atomicAdd(&g_count[e1], 1);
        g_list[e1][p1] = warp; g_wlist[e1][p1] = ex * inv;
    }
}

__global__ void offs_kernel() {
    int s = 0;
#pragma unroll
    for (int e = 0; e < NE; e++) { g_off[e] = s; s += g_count[e]; }
}

// ---------------- pre-passes ------------------------------------------------
// x -> g_xr: tf32-rounded (rna) + sigma-interleaved per 32-chunk
__global__ void round_x_kernel(const float4* __restrict__ in) {
    int n4 = TOK * DID / 4;
    for (int i = blockIdx.x * blockDim.x + threadIdx.x; i < n4;
         i += gridDim.x * blockDim.x) {
        float4 v = in[i];
        int base = (i << 2) & ~31;
        int t = i & 7;                       // SIGMA(4t+j) = j*8+t
        g_xr[base + t]      = f2tf_f(v.x);
        g_xr[base + 8 + t]  = f2tf_f(v.y);
        g_xr[base + 16 + t] = f2tf_f(v.z);
        g_xr[base + 24 + t] = f2tf_f(v.w);
    }
}

// W [e][Kd][Nd] -> g_wt{1,2} [e][Nd][Kd], rounded + sigma-interleaved in k.
// Destination selected by flag INSIDE device code (never a host-side symbol arg).
__global__ __launch_bounds__(256) void transpose_w(
    const float* __restrict__ W, int Kd, int Nd, int which) {
    __shared__ float t[128][33];
    float* Wt = which ? g_wt2 : g_wt1;
    int e = blockIdx.z;
    int n0 = blockIdx.x * 32, k0 = blockIdx.y * 128;
    const float* Wb = W + (size_t)e * Kd * Nd;
    float* Wtb = Wt + (size_t)e * Nd * Kd;
    int tx = threadIdx.x, ty = threadIdx.y;   // (32, 8)
#pragma unroll
    for (int r = 0; r < 16; r++) {
        int k = ty + r * 8;
        t[k][tx] = Wb[(size_t)(k0 + k) * Nd + n0 + tx];
    }
    __syncthreads();
    int kin = SINV(tx);                       // slot tx <- source k SINV(tx)
#pragma unroll
    for (int r = 0; r < 4; r++) {
        int n = ty + r * 8;
        float* dst = Wtb + (size_t)(n0 + n) * Kd + k0;
#pragma unroll
        for (int c = 0; c < 4; c++)
            dst[c * 32 + tx] = f2tf_f(t[c * 32 + kin][n]);
    }
}

// -------- tf32 grouped GEMM: 128x128 CTA, all-LDS.128 fragments, no CVT -----
#define R_STR 36
#define A_F   (128 * R_STR)                 // 4608 floats
#define STAGE_F (2 * A_F)                   // A tile + B tile (both 128x32)
#define GEMM_SMEM (3 * STAGE_F * 4)         // 110592 B (2 CTA/SM = 221KB)

template <int KTOT, int NTOT, bool G2>
__global__ __launch_bounds__(256, 2) void gemm_mma(
    const float* __restrict__ bias,
    float* __restrict__ outp)
{
    const int e = blockIdx.z;
    const int cnt = g_count[e];
    const int m_base = blockIdx.y * 128;
    if (m_base >= cnt) return;
    const int n_base = blockIdx.x * 128;
    const int tid = threadIdx.x;
    const int lane = tid & 31;
    const int wid = tid >> 5;
    const int wm = wid >> 2, wn = wid & 3;
    const int qr = lane >> 2, qc = lane & 3;

    extern __shared__ __align__(16) float sm[];
    const uint32_t sb = smem_u32(sm);

    // A: 2 threads/row, 16 floats each (pre-rounded + sigma'd sources)
    const int row = tid >> 1, hh = tid & 1;
    const float* aptr;
    if (G2) {
        aptr = g_hidden + (size_t)(g_off[e] + m_base + row) * KTOT + hh * 16;
    } else {
        int am = m_base + row; if (am > cnt - 1) am = cnt - 1;
        aptr = g_xr + (size_t)g_list[e][am] * KTOT + hh * 16;
    }
    // B: W^T [e][n][k] sigma'd (g_wt1/g_wt2), same loader shape as A
    const float* wt = G2 ? g_wt2 : g_wt1;
    const float* bptr = wt + ((size_t)e * NTOT + n_base + row) * KTOT + hh * 16;
    const uint32_t ld_dst = (uint32_t)((row * R_STR + hh * 16) * 4);

    auto issue = [&](int c) {
        uint32_t st = sb + (uint32_t)((c % 3) * (STAGE_F * 4));
        const float* ag = aptr + c * 32;
        uint32_t ad = st + ld_dst;
        cpa16(ad, ag); cpa16(ad + 16, ag + 4);
        cpa16(ad + 32, ag + 8); cpa16(ad + 48, ag + 12);
        const float* bg = bptr + c * 32;
        uint32_t bd = st + (uint32_t)(A_F * 4) + ld_dst;
        cpa16(bd, bg); cpa16(bd + 16, bg + 4);
        cpa16(bd + 32, bg + 8); cpa16(bd + 48, bg + 12);
        asm volatile("cp.async.commit_group;\n" ::);
    };

    float acc[4][4][4];
#pragma unroll
    for (int mi = 0; mi < 4; mi++)
#pragma unroll
        for (int nj = 0; nj < 4; nj++)
#pragma unroll
            for (int q = 0; q < 4; q++) acc[mi][nj][q] = 0.f;

    constexpr int NS = KTOT / 32;
    issue(0);
    issue(1);

    for (int c = 0; c < NS; c++) {
        if (c + 1 < NS) {
            asm volatile("cp.async.wait_group 1;\n" ::);
        } else {
            asm volatile("cp.async.wait_group 0;\n" ::);
        }
        __syncthreads();           // stage c visible; stage (c+2)%3 free
        if (c + 2 < NS) issue(c + 2);

        const float* Ac = sm + (c % 3) * STAGE_F;
        const float* Bc = Ac + A_F;
#pragma unroll
        for (int kp = 0; kp < 2; kp++) {
            float4 av[4][2];
#pragma unroll
            for (int mi = 0; mi < 4; mi++) {
                int r0 = wm * 64 + mi * 16 + qr;
                av[mi][0] = *reinterpret_cast<const float4*>(
                    Ac + r0 * R_STR + qc * 8 + kp * 4);
                av[mi][1] = *reinterpret_cast<const float4*>(
                    Ac + (r0 + 8) * R_STR + qc * 8 + kp * 4);
            }
#pragma unroll
            for (int nj = 0; nj < 4; nj++) {
                int nc = wn * 32 + nj * 8 + qr;
                float4 bv = *reinterpret_cast<const float4*>(
                    Bc + nc * R_STR + qc * 8 + kp * 4);
#pragma unroll
                for (int mi = 0; mi < 4; mi++) {
                    mma_tf32x(acc[mi][nj],
                              av[mi][0].x, av[mi][1].x, av[mi][0].y, av[mi][1].y,
                              bv.x, bv.y);
                    mma_tf32x(acc[mi][nj],
                              av[mi][0].z, av[mi][1].z, av[mi][0].w, av[mi][1].w,
                              bv.z, bv.w);
                }
            }
        }
    }

    // ---- epilogue ----
    const int goff = g_off[e];
#pragma unroll
    for (int mi = 0; mi < 4; mi++) {
#pragma unroll
        for (int half = 0; half < 2; half++) {
            int rl = wm * 64 + mi * 16 + qr + half * 8;
            int gm = m_base + rl;
            if (gm >= cnt) continue;
            if (!G2) {
                // hidden written sigma-interleaved + tf32-rounded
                float* hrow = g_hidden + (size_t)(goff + gm) * NTOT;
#pragma unroll
                for (int nj = 0; nj < 4; nj++) {
                    int col = n_base + wn * 32 + nj * 8 + qc * 2;
                    float2 bb = *reinterpret_cast<const float2*>(
                        bias + (size_t)e * NTOT + col);
                    float v0 = fmaxf(acc[mi][nj][half * 2 + 0] + bb.x, 0.f);
                    float v1 = fmaxf(acc[mi][nj][half * 2 + 1] + bb.y, 0.f);
                    int cb = col & ~31;
                    int w = col & 31;
                    hrow[cb + SIGMA(w)]     = f2tf_f(v0);
                    hrow[cb + SIGMA(w + 1)] = f2tf_f(v1);
                }
            } else {
                int t = g_list[e][gm];
                float wf = g_wlist[e][gm];
                float* orow = outp + (size_t)t * NTOT;
#pragma unroll
                for (int nj = 0; nj < 4; nj++) {
                    int col = n_base + wn * 32 + nj * 8 + qc * 2;
                    float2 bb = *reinterpret_cast<const float2*>(
                        bias + (size_t)e * NTOT + col);
                    atomicAdd(&orow[col],     wf * (acc[mi][nj][half * 2 + 0] + bb.x));
                    atomicAdd(&orow[col + 1], wf * (acc[mi][nj][half * 2 + 1] + bb.y));
                }
            }
        }
    }
}

// ---------------- launch -----------------------------------------------------
extern "C" void kernel_launch(void* const* d_in, const int* in_sizes, int n_in,
                              void* d_out, int out_size) {
    const float* x  = (const float*)d_in[0];
    const float* gw = (const float*)d_in[1];
    const float* gb = (const float*)d_in[2];
    const float* W1 = (const float*)d_in[3];   // never modified
    const float* b1 = (const float*)d_in[4];
    const float* W2 = (const float*)d_in[5];   // never modified
    const float* b2 = (const float*)d_in[6];
    float* out = (float*)d_out;

    void* cnt_ptr = nullptr;
    cudaGetSymbolAddress(&cnt_ptr, g_count);
    cudaMemsetAsync(cnt_ptr, 0, sizeof(int) * NE);
    cudaMemsetAsync(d_out, 0, (size_t)out_size * sizeof(float));

    gate_kernel<<<TOK / 8, 256>>>(x, gw, gb);   // gate uses RAW x
    offs_kernel<<<1, 1>>>();
    round_x_kernel<<<2048, 256>>>(reinterpret_cast<const float4*>(x));
    transpose_w<<<dim3(HID / 32, DID / 128, NE), dim3(32, 8)>>>(W1, DID, HID, 0);
    transpose_w<<<dim3(DID / 32, HID / 128, NE), dim3(32, 8)>>>(W2, HID, DID, 1);

    cudaFuncSetAttribute((const void*)gemm_mma<DID, HID, false>,
                         cudaFuncAttributeMaxDynamicSharedMemorySize, GEMM_SMEM);
    cudaFuncSetAttribute((const void*)gemm_mma<HID, DID, true>,
                         cudaFuncAttributeMaxDynamicSharedMemorySize, GEMM_SMEM);

    // GEMM1: gathered g_xr @ g_wt1 -> relu -> hidden (sigma'd + rounded)
    gemm_mma<DID, HID, false><<<dim3(HID / 128, TOK / 128, NE), 256, GEMM_SMEM>>>(
        b1, nullptr);
    // GEMM2: hidden @ g_wt2 -> +b2 -> weighted atomic scatter into out
    gemm_mma<HID, DID, true><<<dim3(DID / 128, TOK / 128, NE), 256, GEMM_SMEM>>>(
        b2, out);
}

// round 16
// speedup vs baseline: 22.6900x; 1.7017x over previous
#include <cuda_runtime.h>
#include <cuda_fp16.h>
#include <cstdint>

#define TOK 16384
#define DID 1024
#define HID 4096
#define NE  8

// fp16 sigma-interleave within a 32-half chunk, matched to m16n8k16 fragments:
// slot(k) = qc*8 + hi*4 + c*2 + b, where qc=((k&7)>>1), hi=(k>>4)&1, c=(k>>3)&1, b=k&1
#define SLOT_H(k)  (((((k) & 7) >> 1) << 3) | ((((k) >> 4) & 1) << 2) | ((((k) >> 3) & 1) << 1) | ((k) & 1))
// inverse: k(s) = hi*16 + c*8 + qc*2 + b with qc=s>>3, hi=(s>>2)&1, c=(s>>1)&1, b=s&1
#define SINV_H(s)  (((((s) >> 2) & 1) << 4) | ((((s) >> 1) & 1) << 3) | ((((s) >> 3) & 3) << 1) | ((s) & 1))

// ------ scratch (~430MB; symbols referenced ONLY inside device code) --------
__device__ int   g_count[NE];
__device__ int   g_off[NE];
__device__ __align__(16) int   g_list[NE][TOK];
__device__ __align__(16) float g_wlist[NE][TOK];
__device__ __align__(256) __half g_xh[(size_t)TOK * DID];                  // 32MB
__device__ __align__(256) __half g_wt1[(size_t)NE * HID * DID];            // 64MB
__device__ __align__(256) __half g_wt2[(size_t)NE * DID * HID];            // 64MB
__device__ __align__(256) __half g_hidden[(size_t)(2 * TOK + 128) * HID];  // 269MB

// ---------------- helpers ---------------------------------------------------
__device__ __forceinline__ uint32_t smem_u32(const void* p) {
    uint32_t a;
    asm("{ .reg .u64 t; cvta.to.shared.u64 t, %1; cvt.u32.u64 %0, t; }" : "=r"(a) : "l"(p));
    return a;
}
__device__ __forceinline__ void cpa16(uint32_t s, const void* g) {
    asm volatile("cp.async.cg.shared.global [%0], [%1], 16;\n" ::"r"(s), "l"(g));
}
__device__ __forceinline__ void mma_f16(float* c, uint32_t a0, uint32_t a1,
                                        uint32_t a2, uint32_t a3,
                                        uint32_t b0, uint32_t b1) {
    asm volatile(
        "mma.sync.aligned.m16n8k16.row.col.f32.f16.f16.f32 "
        "{%0,%1,%2,%3},{%4,%5,%6,%7},{%8,%9},{%0,%1,%2,%3};"
        : "+f"(c[0]), "+f"(c[1]), "+f"(c[2]), "+f"(c[3])
        : "r"(a0), "r"(a1), "r"(a2), "r"(a3), "r"(b0), "r"(b1));
}

// ---------------- gate (RAW x: selection identical to reference) ------------
__global__ void gate_kernel(const float* __restrict__ x,
                            const float* __restrict__ gw,
                            const float* __restrict__ gb) {
    int warp = (blockIdx.x * blockDim.x + threadIdx.x) >> 5;
    int lane = threadIdx.x & 31;
    if (warp >= TOK) return;
    const float* xr = x + (size_t)warp * DID;
    float p[NE];
#pragma unroll
    for (int e = 0; e < NE; e++) p[e] = 0.f;
#pragma unroll 4
    for (int i = 0; i < DID / 32; i++) {
        int d = i * 32 + lane;
        float xv = xr[d];
        const float4* g4 = reinterpret_cast<const float4*>(gw + (size_t)d * NE);
        float4 g0 = g4[0], g1 = g4[1];
        p[0] += xv * g0.x; p[1] += xv * g0.y; p[2] += xv * g0.z; p[3] += xv * g0.w;
        p[4] += xv * g1.x; p[5] += xv * g1.y; p[6] += xv * g1.z; p[7] += xv * g1.w;
    }
#pragma unroll
    for (int e = 0; e < NE; e++)
#pragma unroll
        for (int o = 16; o > 0; o >>= 1) p[e] += __shfl_xor_sync(0xffffffffu, p[e], o);
    if (lane == 0) {
        float l[NE];
#pragma unroll
        for (int e = 0; e < NE; e++) l[e] = p[e] + gb[e];
        int e0 = 0, e1 = -1;
        float b0 = l[0], b1 = -3.0e38f;
#pragma unroll
        for (int e = 1; e < NE; e++) {
            float v = l[e];
            if (v > b0)      { b1 = b0; e1 = e0; b0 = v; e0 = e; }
            else if (v > b1) { b1 = v;  e1 = e; }
        }
        float ex = expf(b1 - b0);
        float inv = 1.f / (1.f + ex);
        int p0 = atomicAdd(&g_count[e0], 1);
        g_list[e0][p0] = warp; g_wlist[e0][p0] = inv;
        int p1 = atomicAdd(&g_count[e1], 1);
        g_list[e1][p1] = warp; g_wlist[e1][p1] = ex * inv;
    }
}

__global__ void offs_kernel() {
    int s = 0;
#pragma unroll
    for (int e = 0; e < NE; e++) { g_off[e] = s; s += g_count[e]; }
}

// ---------------- pre-passes ------------------------------------------------
// x -> g_xh: fp16 (rn), sigma16-interleaved per 32-chunk
__global__ void round_x_kernel(const float4* __restrict__ in) {
    int n4 = TOK * DID / 4;
    for (int i = blockIdx.x * blockDim.x + threadIdx.x; i < n4;
         i += gridDim.x * blockDim.x) {
        float4 v = in[i];
        int base = (i << 2) & ~31;           // chunk-aligned element index
        int k0 = (i << 2) & 31;              // even
        __half2 lo = __floats2half2_rn(v.x, v.y);
        __half2 hi = __floats2half2_rn(v.z, v.w);
        *reinterpret_cast<__half2*>(&g_xh[base + SLOT_H(k0)])     = lo;
        *reinterpret_cast<__half2*>(&g_xh[base + SLOT_H(k0 + 2)]) = hi;
    }
}

// W [e][Kd][Nd] -> g_wt{1,2} [e][Nd][Kd] fp16, sigma16-interleaved in k.
__global__ __launch_bounds__(256) void transpose_w(
    const float* __restrict__ W, int Kd, int Nd, int which) {
    __shared__ float t[128][33];
    __half* Wt = which ? g_wt2 : g_wt1;
    int e = blockIdx.z;
    int n0 = blockIdx.x * 32, k0 = blockIdx.y * 128;
    const float* Wb = W + (size_t)e * Kd * Nd;
    __half* Wtb = Wt + (size_t)e * Nd * Kd;
    int tx = threadIdx.x, ty = threadIdx.y;   // (32, 8)
#pragma unroll
    for (int r = 0; r < 16; r++) {
        int k = ty + r * 8;
        t[k][tx] = Wb[(size_t)(k0 + k) * Nd + n0 + tx];
    }
    __syncthreads();
    int kin = SINV_H(tx);                     // slot tx <- source k
#pragma unroll
    for (int r = 0; r < 4; r++) {
        int n = ty + r * 8;
        __half* dst = Wtb + (size_t)(n0 + n) * Kd + k0;
#pragma unroll
        for (int c = 0; c < 4; c++)
            dst[c * 32 + tx] = __float2half_rn(t[c * 32 + kin][n]);
    }
}

// -------- fp16 grouped GEMM: 128x128 CTA, all-LDS.128 fragments -------------
#define A_H    (128 * 32)                   // 4096 halves per tile per chunk
#define STAGE_H (2 * A_H)                   // 8192 halves = 16KB
#define GEMM_SMEM (3 * STAGE_H * 2)         // 49152 B

template <int KTOT, int NTOT, bool G2>
__global__ __launch_bounds__(256, 2) void gemm_mma(
    const float* __restrict__ bias,
    float* __restrict__ outp)
{
    const int e = blockIdx.z;
    const int cnt = g_count[e];
    const int m_base = blockIdx.y * 128;
    if (m_base >= cnt) return;
    const int n_base = blockIdx.x * 128;
    const int tid = threadIdx.x;
    const int lane = tid & 31;
    const int wid = tid >> 5;
    const int wm = wid >> 2, wn = wid & 3;
    const int qr = lane >> 2, qc = lane & 3;

    extern __shared__ __align__(16) __half smh[];
    const uint32_t sb = smem_u32(smh);

    // A: 2 threads/row, 16 halves (32B) each
    const int row = tid >> 1, hh = tid & 1;
    const __half* aptr;
    if (G2) {
        aptr = g_hidden + (size_t)(g_off[e] + m_base + row) * KTOT + hh * 16;
    } else {
        int am = m_base + row; if (am > cnt - 1) am = cnt - 1;
        aptr = g_xh + (size_t)g_list[e][am] * KTOT + hh * 16;
    }
    const __half* wt = G2 ? g_wt2 : g_wt1;
    const __half* bptr = wt + ((size_t)e * NTOT + n_base + row) * KTOT + hh * 16;
    const uint32_t ld_dst = (uint32_t)((row * 32 + hh * 16) * 2);  // bytes

    auto issue = [&](int c) {
        uint32_t st = sb + (uint32_t)((c % 3) * (STAGE_H * 2));
        const __half* ag = aptr + c * 32;
        uint32_t ad = st + ld_dst;
        cpa16(ad, ag); cpa16(ad + 16, ag + 8);
        const __half* bg = bptr + c * 32;
        uint32_t bd = st + (uint32_t)(A_H * 2) + ld_dst;
        cpa16(bd, bg); cpa16(bd + 16, bg + 8);
        asm volatile("cp.async.commit_group;\n" ::);
    };

    float acc[4][4][4];
#pragma unroll
    for (int mi = 0; mi < 4; mi++)
#pragma unroll
        for (int nj = 0; nj < 4; nj++)
#pragma unroll
            for (int q = 0; q < 4; q++) acc[mi][nj][q] = 0.f;

    constexpr int NS = KTOT / 32;
    issue(0);
    issue(1);

    for (int c = 0; c < NS; c++) {
        if (c + 1 < NS) {
            asm volatile("cp.async.wait_group 1;\n" ::);
        } else {
            asm volatile("cp.async.wait_group 0;\n" ::);
        }
        __syncthreads();           // stage c visible; stage (c+2)%3 free
        if (c + 2 < NS) issue(c + 2);

        const __half* Ac = smh + (c % 3) * STAGE_H;
        const __half* Bc = Ac + A_H;
        uint4 av[4][2];
#pragma unroll
        for (int mi = 0; mi < 4; mi++) {
            int r0 = wm * 64 + mi * 16 + qr;
            av[mi][0] = *reinterpret_cast<const uint4*>(Ac + r0 * 32 + qc * 8);
            av[mi][1] = *reinterpret_cast<const uint4*>(Ac + (r0 + 8) * 32 + qc * 8);
        }
#pragma unroll
        for (int nj = 0; nj < 4; nj++) {
            int nc = wn * 32 + nj * 8 + qr;
            uint4 bv = *reinterpret_cast<const uint4*>(Bc + nc * 32 + qc * 8);
#pragma unroll
            for (int mi = 0; mi < 4; mi++) {
                // kp0: k 0..15  (x = k(2qc,2qc+1), y = k(2qc+8,2qc+9))
                mma_f16(acc[mi][nj], av[mi][0].x, av[mi][1].x,
                        av[mi][0].y, av[mi][1].y, bv.x, bv.y);
                // kp1: k 16..31 (z, w)
                mma_f16(acc[mi][nj], av[mi][0].z, av[mi][1].z,
                        av[mi][0].w, av[mi][1].w, bv.z, bv.w);
            }
        }
    }

    // ---- epilogue ----
    const int goff = g_off[e];
#pragma unroll
    for (int mi = 0; mi < 4; mi++) {
#pragma unroll
        for (int half = 0; half < 2; half++) {
            int rl = wm * 64 + mi * 16 + qr + half * 8;
            int gm = m_base + rl;
            if (gm >= cnt) continue;
            if (!G2) {
                // hidden written fp16 + sigma16-interleaved (k-dim of GEMM2)
                __half* hrow = g_hidden + (size_t)(goff + gm) * NTOT;
#pragma unroll
                for (int nj = 0; nj < 4; nj++) {
                    int col = n_base + wn * 32 + nj * 8 + qc * 2;
                    float2 bb = *reinterpret_cast<const float2*>(
                        bias + (size_t)e * NTOT + col);
                    float v0 = fmaxf(acc[mi][nj][half * 2 + 0] + bb.x, 0.f);
                    float v1 = fmaxf(acc[mi][nj][half * 2 + 1] + bb.y, 0.f);
                    int cb = col & ~31;
                    int w = col & 31;          // even -> slot pair contiguous
                    *reinterpret_cast<__half2*>(&hrow[cb + SLOT_H(w)]) =
                        __floats2half2_rn(v0, v1);
                }
            } else {
                int t = g_list[e][gm];
                float wf = g_wlist[e][gm];
                float* orow = outp + (size_t)t * NTOT;
#pragma unroll
                for (int nj = 0; nj < 4; nj++) {
                    int col = n_base + wn * 32 + nj * 8 + qc * 2;
                    float2 bb = *reinterpret_cast<const float2*>(
                        bias + (size_t)e * NTOT + col);
                    atomicAdd(&orow[col],     wf * (acc[mi][nj][half * 2 + 0] + bb.x));
                    atomicAdd(&orow[col + 1], wf * (acc[mi][nj][half * 2 + 1] + bb.y));
                }
            }
        }
    }
}

// ---------------- launch -----------------------------------------------------
extern "C" void kernel_launch(void* const* d_in, const int* in_sizes, int n_in,
                              void* d_out, int out_size) {
    const float* x  = (const float*)d_in[0];
    const float* gw = (const float*)d_in[1];
    const float* gb = (const float*)d_in[2];
    const float* W1 = (const float*)d_in[3];   // never modified
    const float* b1 = (const float*)d_in[4];
    const float* W2 = (const float*)d_in[5];   // never modified
    const float* b2 = (const float*)d_in[6];
    float* out = (float*)d_out;

    void* cnt_ptr = nullptr;
    cudaGetSymbolAddress(&cnt_ptr, g_count);
    cudaMemsetAsync(cnt_ptr, 0, sizeof(int) * NE);
    cudaMemsetAsync(d_out, 0, (size_t)out_size * sizeof(float));

    gate_kernel<<<TOK / 8, 256>>>(x, gw, gb);   // gate uses RAW x
    offs_kernel<<<1, 1>>>();
    round_x_kernel<<<2048, 256>>>(reinterpret_cast<const float4*>(x));
    transpose_w<<<dim3(HID / 32, DID / 128, NE), dim3(32, 8)>>>(W1, DID, HID, 0);
    transpose_w<<<dim3(DID / 32, HID / 128, NE), dim3(32, 8)>>>(W2, HID, DID, 1);

    cudaFuncSetAttribute((const void*)gemm_mma<DID, HID, false>,
                         cudaFuncAttributeMaxDynamicSharedMemorySize, GEMM_SMEM);
    cudaFuncSetAttribute((const void*)gemm_mma<HID, DID, true>,
                         cudaFuncAttributeMaxDynamicSharedMemorySize, GEMM_SMEM);

    // GEMM1: gathered g_xh @ g_wt1 -> relu -> hidden (fp16, sigma'd)
    gemm_mma<DID, HID, false><<<dim3(HID / 128, TOK / 128, NE), 256, GEMM_SMEM>>>(
        b1, nullptr);
    // GEMM2: hidden @ g_wt2 -> +b2 -> weighted atomic scatter into out
    gemm_mma<HID, DID, true><<<dim3(DID / 128, TOK / 128, NE), 256, GEMM_SMEM>>>(
        b2, out);
}